// round 6
// baseline (speedup 1.0000x reference)
#include <cuda_runtime.h>
#include <cstdint>

// Problem dims
#define S_LEN 2048
#define BATCH 128
#define EDIM  128
#define LDIM  128
#define GDIM  512   // 4*LDIM, gate order: f, i, g, o

typedef unsigned long long ull;

// 512 MB scratch for precomputed input projections xg[t][b][512] (bias-folded)
__device__ float g_xg[(size_t)S_LEN * BATCH * GDIM];

// ---------------- packed fp32x2 helpers ----------------
__device__ __forceinline__ ull pack2(float a, float b) {
    ull r;
    asm("mov.b64 %0, {%1, %2};" : "=l"(r) : "f"(a), "f"(b));
    return r;
}
__device__ __forceinline__ float lo32(ull v) {
    float a, b;
    asm("mov.b64 {%0, %1}, %2;" : "=f"(a), "=f"(b) : "l"(v));
    return a;
}
__device__ __forceinline__ float hi32(ull v) {
    float a, b;
    asm("mov.b64 {%0, %1}, %2;" : "=f"(a), "=f"(b) : "l"(v));
    return b;
}
#define FFMA2(acc, a, b) asm("fma.rn.f32x2 %0, %1, %2, %0;" : "+l"(acc) : "l"(a), "l"(b))

// ---------------- fast activations via MUFU.TANH ----------------
__device__ __forceinline__ float fast_tanh(float x) {
    float y;
    asm("tanh.approx.f32 %0, %1;" : "=f"(y) : "f"(x));
    return y;
}
__device__ __forceinline__ float fast_sigmoid(float x) {
    return fmaf(0.5f, fast_tanh(0.5f * x), 0.5f);
}

// =====================================================================
// Kernel 1: xg = x @ Wi + (bi + bh) via tf32 mma.sync  (tensor pipe)
// [M=S*B=262144, N=512, K=128]; block tile 128x256, 256 threads,
// full K resident in smem (As 128x132, Bs 128x264 — conflict-free pads).
// 8 warps as 2(m) x 4(n); warp tile 64x64; m16n8k8 tf32 fragments.
// (measured ~330us; unchanged this round)
// =====================================================================
__global__ __launch_bounds__(256) void xg_gemm_tf32(
    const float* __restrict__ x,
    const float* __restrict__ Wi,
    const float* __restrict__ bi,
    const float* __restrict__ bh)
{
    extern __shared__ float sm[];
    float* As     = sm;                    // [128][132] tf32 bits
    float* Bs     = sm + 128 * 132;        // [128][264] tf32 bits
    float* bias_s = Bs + 128 * 264;        // [256]

    const int tid = threadIdx.x;
    const int bm  = blockIdx.x;            // 2048 M tiles
    const int bn  = blockIdx.y;            // 2 N tiles

    {
        const int c  = 4 * (tid & 31);
        const int r0 = tid >> 5;
        #pragma unroll
        for (int i = 0; i < 16; i++) {
            const int m = r0 + 8 * i;
            float4 v = *(const float4*)(x + (size_t)(bm * 128 + m) * EDIM + c);
            uint4 u;
            asm("cvt.rna.tf32.f32 %0, %1;" : "=r"(u.x) : "f"(v.x));
            asm("cvt.rna.tf32.f32 %0, %1;" : "=r"(u.y) : "f"(v.y));
            asm("cvt.rna.tf32.f32 %0, %1;" : "=r"(u.z) : "f"(v.z));
            asm("cvt.rna.tf32.f32 %0, %1;" : "=r"(u.w) : "f"(v.w));
            *(uint4*)(As + m * 132 + c) = u;
        }
    }
    {
        const int c  = 4 * (tid & 63);
        const int k0 = tid >> 6;
        #pragma unroll
        for (int i = 0; i < 32; i++) {
            const int k = k0 + 4 * i;
            float4 v = *(const float4*)(Wi + (size_t)k * GDIM + bn * 256 + c);
            uint4 u;
            asm("cvt.rna.tf32.f32 %0, %1;" : "=r"(u.x) : "f"(v.x));
            asm("cvt.rna.tf32.f32 %0, %1;" : "=r"(u.y) : "f"(v.y));
            asm("cvt.rna.tf32.f32 %0, %1;" : "=r"(u.z) : "f"(v.z));
            asm("cvt.rna.tf32.f32 %0, %1;" : "=r"(u.w) : "f"(v.w));
            *(uint4*)(Bs + k * 264 + c) = u;
        }
    }
    bias_s[tid] = bi[bn * 256 + tid] + bh[bn * 256 + tid];
    __syncthreads();

    const int lane = tid & 31;
    const int w    = tid >> 5;
    const int mb   = (w & 1) * 64;
    const int nb   = (w >> 1) * 64;
    const int r    = lane >> 2;
    const int cq   = lane & 3;

    float acc[4][8][4];
    #pragma unroll
    for (int f = 0; f < 4; f++)
        #pragma unroll
        for (int g = 0; g < 8; g++)
            #pragma unroll
            for (int i = 0; i < 4; i++) acc[f][g][i] = 0.f;

    #pragma unroll 4
    for (int s = 0; s < 16; s++) {
        const int k0 = 8 * s;
        uint32_t a[4][4];
        #pragma unroll
        for (int f = 0; f < 4; f++) {
            const float* ap = As + (mb + f * 16 + r) * 132 + k0 + cq;
            a[f][0] = __float_as_uint(ap[0]);
            a[f][1] = __float_as_uint(ap[8 * 132]);
            a[f][2] = __float_as_uint(ap[4]);
            a[f][3] = __float_as_uint(ap[8 * 132 + 4]);
        }
        uint32_t b[8][2];
        #pragma unroll
        for (int g = 0; g < 8; g++) {
            const float* bp = Bs + (k0 + cq) * 264 + nb + g * 8 + r;
            b[g][0] = __float_as_uint(bp[0]);
            b[g][1] = __float_as_uint(bp[4 * 264]);
        }
        #pragma unroll
        for (int f = 0; f < 4; f++)
            #pragma unroll
            for (int g = 0; g < 8; g++)
                asm("mma.sync.aligned.m16n8k8.row.col.f32.tf32.tf32.f32 "
                    "{%0,%1,%2,%3}, {%4,%5,%6,%7}, {%8,%9}, {%0,%1,%2,%3};"
                    : "+f"(acc[f][g][0]), "+f"(acc[f][g][1]),
                      "+f"(acc[f][g][2]), "+f"(acc[f][g][3])
                    : "r"(a[f][0]), "r"(a[f][1]), "r"(a[f][2]), "r"(a[f][3]),
                      "r"(b[g][0]), "r"(b[g][1]));
    }

    #pragma unroll
    for (int f = 0; f < 4; f++) {
        const int mrow = bm * 128 + mb + f * 16 + r;
        #pragma unroll
        for (int g = 0; g < 8; g++) {
            const int ncol = nb + g * 8 + 2 * cq;
            const float b0 = bias_s[ncol];
            const float b1 = bias_s[ncol + 1];
            float* d0 = g_xg + (size_t)mrow * GDIM + bn * 256 + ncol;
            *(float2*)d0 = make_float2(acc[f][g][0] + b0, acc[f][g][1] + b1);
            float* d1 = d0 + (size_t)8 * GDIM;
            *(float2*)d1 = make_float2(acc[f][g][2] + b0, acc[f][g][3] + b1);
        }
    }
}

// =====================================================================
// Kernel 2: persistent per-batch LSTM recurrence + classifier head.
// 128 blocks (1 batch each), 256 threads. Warp-local gate pairing:
//   lane-pair (even,odd) owns cell = warp*16 + lane/2;
//   even lane: columns (f_c, g_c); odd lane: (i_c, o_c).
// Gate exchange via shfl.xor(1); cell update computed redundantly by
// both lanes (no idle threads, no smem exchange). h double-buffered
// -> exactly ONE __syncthreads per step.
// Wh rows 32..127 register-resident per column (192 regs), rows 0..31
// streamed from smem. Activations via MUFU.TANH.
// =====================================================================
#define SM_Q   8    // 8 quads  -> rows 0..31 in smem
#define REG_Q  24   // 24 quads -> rows 32..127 in registers

__global__ __launch_bounds__(256, 1) void lstm_rec(
    const float* __restrict__ Wh,
    const float* __restrict__ Wc,
    const float* __restrict__ bc,
    float* __restrict__ out)
{
    extern __shared__ char smraw[];
    ulonglong2* Ws = (ulonglong2*)smraw;                 // [SM_Q][512]
    float* h0 = (float*)(smraw + SM_Q * 512 * 16);       // [128] buffer 0
    float* h1 = h0 + 128;                                // [128] buffer 1

    const int p    = threadIdx.x;   // 0..255
    const int b    = blockIdx.x;    // batch element
    const int lane = p & 31;
    const int wid  = p >> 5;
    const int cell = (wid << 4) + (lane >> 1);   // 0..127
    const int odd  = lane & 1;
    // even lane: f (cell), g (256+cell); odd lane: i (128+cell), o (384+cell)
    const int ca = odd ? (128 + cell) : cell;
    const int cb = odd ? (384 + cell) : (256 + cell);

    // ---- stage Wh rows 0..31 into smem (k-quad packed per column) ----
    // (coverage by tid: columns p and p+256 — covers all 512 columns)
    #pragma unroll
    for (int q = 0; q < SM_Q; q++) {
        const int k0 = 4 * q;
        #pragma unroll
        for (int s = 0; s < 2; s++) {
            const int col = p + s * 256;
            ulonglong2 u;
            u.x = pack2(__ldg(&Wh[(k0 + 0) * GDIM + col]), __ldg(&Wh[(k0 + 1) * GDIM + col]));
            u.y = pack2(__ldg(&Wh[(k0 + 2) * GDIM + col]), __ldg(&Wh[(k0 + 3) * GDIM + col]));
            Ws[q * 512 + col] = u;
        }
    }
    // ---- stage Wh rows 32..127 into registers for this thread's columns ----
    ulonglong2 wra[REG_Q], wrb[REG_Q];
    #pragma unroll
    for (int q = 0; q < REG_Q; q++) {
        const int k0 = 4 * SM_Q + 4 * q;
        wra[q].x = pack2(__ldg(&Wh[(k0 + 0) * GDIM + ca]), __ldg(&Wh[(k0 + 1) * GDIM + ca]));
        wra[q].y = pack2(__ldg(&Wh[(k0 + 2) * GDIM + ca]), __ldg(&Wh[(k0 + 3) * GDIM + ca]));
        wrb[q].x = pack2(__ldg(&Wh[(k0 + 0) * GDIM + cb]), __ldg(&Wh[(k0 + 1) * GDIM + cb]));
        wrb[q].y = pack2(__ldg(&Wh[(k0 + 2) * GDIM + cb]), __ldg(&Wh[(k0 + 3) * GDIM + cb]));
    }

    if (p < 128) h0[p] = 0.f;   // t=0 reads buffer 0
    float c_val = 0.f;
    __syncthreads();

    const float* xga = g_xg + (size_t)b * GDIM + ca;
    const float* xgb = g_xg + (size_t)b * GDIM + cb;
    const size_t stepStride = (size_t)BATCH * GDIM;
    float xga_c = __ldg(xga);
    float xga_n = __ldg(xga + stepStride);
    float xgb_c = __ldg(xgb);
    float xgb_n = __ldg(xgb + stepStride);

    const ulonglong2* wsa = Ws + ca;
    const ulonglong2* wsb = Ws + cb;

    for (int t = 0; t < S_LEN; t++) {
        const float* h_rd = (t & 1) ? h1 : h0;
        float*       h_wr = (t & 1) ? h0 : h1;
        const ulonglong2* h4 = (const ulonglong2*)h_rd;

        // prefetch xg for t+2 (branch-free clamped index)
        const size_t off = (size_t)((t + 2 < S_LEN) ? (t + 2) : (S_LEN - 1)) * stepStride;
        const float xga_p = __ldg(xga + off);
        const float xgb_p = __ldg(xgb + off);

        ull accA0 = 0ULL, accA1 = 0ULL, accB0 = 0ULL, accB1 = 0ULL;
        // rows 0..31 from smem
        #pragma unroll
        for (int q = 0; q < SM_Q; q++) {
            ulonglong2 hv = h4[q];
            ulonglong2 wa = wsa[q * 512];
            ulonglong2 wb = wsb[q * 512];
            FFMA2(accA0, wa.x, hv.x);
            FFMA2(accA1, wa.y, hv.y);
            FFMA2(accB0, wb.x, hv.x);
            FFMA2(accB1, wb.y, hv.y);
        }
        // rows 32..127 from registers
        #pragma unroll
        for (int q = 0; q < REG_Q; q++) {
            ulonglong2 hv = h4[SM_Q + q];
            FFMA2(accA0, wra[q].x, hv.x);
            FFMA2(accA1, wra[q].y, hv.y);
            FFMA2(accB0, wrb[q].x, hv.x);
            FFMA2(accB1, wrb[q].y, hv.y);
        }
        float va = (lo32(accA0) + lo32(accA1)) + (hi32(accA0) + hi32(accA1)) + xga_c;
        float vb = (lo32(accB0) + lo32(accB1)) + (hi32(accB0) + hi32(accB1)) + xgb_c;
        xga_c = xga_n; xga_n = xga_p;
        xgb_c = xgb_n; xgb_n = xgb_p;

        // activations: col a is always a sigmoid gate (f or i);
        // col b: even lane -> tanh (g), odd lane -> sigmoid (o)
        float act_a = fast_sigmoid(va);
        float act_b = odd ? fast_sigmoid(vb) : fast_tanh(vb);

        // exchange with the partner lane
        float ra = __shfl_xor_sync(0xffffffffu, act_a, 1);
        float rb = __shfl_xor_sync(0xffffffffu, act_b, 1);

        const float f_ = odd ? ra    : act_a;
        const float i_ = odd ? act_a : ra;
        const float g_ = odd ? rb    : act_b;
        const float o_ = odd ? act_b : rb;

        c_val = fmaf(f_, c_val, i_ * g_);        // identical in both lanes
        const float h_new = o_ * fast_tanh(c_val);

        if (!odd) h_wr[cell] = h_new;
        __syncthreads();                          // ONE barrier per step
    }

    // final h is in buffer 0 (t=2047 writes h0)
    if (p < 2) {
        float s = __ldg(&bc[p]);
        #pragma unroll 8
        for (int l = 0; l < 128; l++) s += h0[l] * __ldg(&Wc[l * 2 + p]);
        out[b * 2 + p] = s;
    }
}

// =====================================================================
extern "C" void kernel_launch(void* const* d_in, const int* in_sizes, int n_in,
                              void* d_out, int out_size)
{
    const float* x  = (const float*)d_in[0];
    const float* Wi = (const float*)d_in[1];
    const float* bi = (const float*)d_in[2];
    const float* Wh = (const float*)d_in[3];
    const float* bh = (const float*)d_in[4];
    const float* Wc = (const float*)d_in[5];
    const float* bc = (const float*)d_in[6];
    float* out = (float*)d_out;

    const int smemA = (128 * 132 + 128 * 264 + 256) * (int)sizeof(float);  // 203776
    const int smemR = SM_Q * 512 * 16 + 256 * (int)sizeof(float);          // 66560

    cudaFuncSetAttribute(xg_gemm_tf32, cudaFuncAttributeMaxDynamicSharedMemorySize, smemA);
    cudaFuncSetAttribute(lstm_rec,     cudaFuncAttributeMaxDynamicSharedMemorySize, smemR);

    dim3 gridA((S_LEN * BATCH) / 128, GDIM / 256);
    xg_gemm_tf32<<<gridA, 256, smemA>>>(x, Wi, bi, bh);
    lstm_rec<<<BATCH, 256, smemR>>>(Wh, Wc, bc, out);
}

// round 8
// speedup vs baseline: 1.2837x; 1.2837x over previous
#include <cuda_runtime.h>
#include <cstdint>

// Problem dims
#define S_LEN 2048
#define BATCH 128
#define EDIM  128
#define LDIM  128
#define GDIM  512   // 4*LDIM, gate order: f, i, g, o

typedef unsigned long long ull;

// 512 MB scratch for precomputed input projections xg[t][b][512] (bias-folded)
__device__ float g_xg[(size_t)S_LEN * BATCH * GDIM];

// ---------------- packed fp32x2 helpers ----------------
__device__ __forceinline__ ull pack2(float a, float b) {
    ull r;
    asm("mov.b64 %0, {%1, %2};" : "=l"(r) : "f"(a), "f"(b));
    return r;
}
__device__ __forceinline__ float lo32(ull v) {
    float a, b;
    asm("mov.b64 {%0, %1}, %2;" : "=f"(a), "=f"(b) : "l"(v));
    return a;
}
__device__ __forceinline__ float hi32(ull v) {
    float a, b;
    asm("mov.b64 {%0, %1}, %2;" : "=f"(a), "=f"(b) : "l"(v));
    return b;
}
#define FFMA2(acc, a, b) asm("fma.rn.f32x2 %0, %1, %2, %0;" : "+l"(acc) : "l"(a), "l"(b))

// ---------------- fast activations via MUFU.TANH ----------------
__device__ __forceinline__ float fast_tanh(float x) {
    float y;
    asm("tanh.approx.f32 %0, %1;" : "=f"(y) : "f"(x));
    return y;
}
__device__ __forceinline__ float fast_sigmoid(float x) {
    return fmaf(0.5f, fast_tanh(0.5f * x), 0.5f);
}

// =====================================================================
// Kernel 1: xg = x @ Wi + (bi + bh) via tf32 mma.sync  (tensor pipe)
// [M=S*B=262144, N=512, K=128]; block tile 128x256, 256 threads,
// full K resident in smem (As 128x132, Bs 128x264 — conflict-free pads).
// 8 warps as 2(m) x 4(n); warp tile 64x64; m16n8k8 tf32 fragments.
// (measured ~330us; unchanged)
// =====================================================================
__global__ __launch_bounds__(256) void xg_gemm_tf32(
    const float* __restrict__ x,
    const float* __restrict__ Wi,
    const float* __restrict__ bi,
    const float* __restrict__ bh)
{
    extern __shared__ float sm[];
    float* As     = sm;                    // [128][132] tf32 bits
    float* Bs     = sm + 128 * 132;        // [128][264] tf32 bits
    float* bias_s = Bs + 128 * 264;        // [256]

    const int tid = threadIdx.x;
    const int bm  = blockIdx.x;            // 2048 M tiles
    const int bn  = blockIdx.y;            // 2 N tiles

    {
        const int c  = 4 * (tid & 31);
        const int r0 = tid >> 5;
        #pragma unroll
        for (int i = 0; i < 16; i++) {
            const int m = r0 + 8 * i;
            float4 v = *(const float4*)(x + (size_t)(bm * 128 + m) * EDIM + c);
            uint4 u;
            asm("cvt.rna.tf32.f32 %0, %1;" : "=r"(u.x) : "f"(v.x));
            asm("cvt.rna.tf32.f32 %0, %1;" : "=r"(u.y) : "f"(v.y));
            asm("cvt.rna.tf32.f32 %0, %1;" : "=r"(u.z) : "f"(v.z));
            asm("cvt.rna.tf32.f32 %0, %1;" : "=r"(u.w) : "f"(v.w));
            *(uint4*)(As + m * 132 + c) = u;
        }
    }
    {
        const int c  = 4 * (tid & 63);
        const int k0 = tid >> 6;
        #pragma unroll
        for (int i = 0; i < 32; i++) {
            const int k = k0 + 4 * i;
            float4 v = *(const float4*)(Wi + (size_t)k * GDIM + bn * 256 + c);
            uint4 u;
            asm("cvt.rna.tf32.f32 %0, %1;" : "=r"(u.x) : "f"(v.x));
            asm("cvt.rna.tf32.f32 %0, %1;" : "=r"(u.y) : "f"(v.y));
            asm("cvt.rna.tf32.f32 %0, %1;" : "=r"(u.z) : "f"(v.z));
            asm("cvt.rna.tf32.f32 %0, %1;" : "=r"(u.w) : "f"(v.w));
            *(uint4*)(Bs + k * 264 + c) = u;
        }
    }
    bias_s[tid] = bi[bn * 256 + tid] + bh[bn * 256 + tid];
    __syncthreads();

    const int lane = tid & 31;
    const int w    = tid >> 5;
    const int mb   = (w & 1) * 64;
    const int nb   = (w >> 1) * 64;
    const int r    = lane >> 2;
    const int cq   = lane & 3;

    float acc[4][8][4];
    #pragma unroll
    for (int f = 0; f < 4; f++)
        #pragma unroll
        for (int g = 0; g < 8; g++)
            #pragma unroll
            for (int i = 0; i < 4; i++) acc[f][g][i] = 0.f;

    #pragma unroll 4
    for (int s = 0; s < 16; s++) {
        const int k0 = 8 * s;
        uint32_t a[4][4];
        #pragma unroll
        for (int f = 0; f < 4; f++) {
            const float* ap = As + (mb + f * 16 + r) * 132 + k0 + cq;
            a[f][0] = __float_as_uint(ap[0]);
            a[f][1] = __float_as_uint(ap[8 * 132]);
            a[f][2] = __float_as_uint(ap[4]);
            a[f][3] = __float_as_uint(ap[8 * 132 + 4]);
        }
        uint32_t b[8][2];
        #pragma unroll
        for (int g = 0; g < 8; g++) {
            const float* bp = Bs + (k0 + cq) * 264 + nb + g * 8 + r;
            b[g][0] = __float_as_uint(bp[0]);
            b[g][1] = __float_as_uint(bp[4 * 264]);
        }
        #pragma unroll
        for (int f = 0; f < 4; f++)
            #pragma unroll
            for (int g = 0; g < 8; g++)
                asm("mma.sync.aligned.m16n8k8.row.col.f32.tf32.tf32.f32 "
                    "{%0,%1,%2,%3}, {%4,%5,%6,%7}, {%8,%9}, {%0,%1,%2,%3};"
                    : "+f"(acc[f][g][0]), "+f"(acc[f][g][1]),
                      "+f"(acc[f][g][2]), "+f"(acc[f][g][3])
                    : "r"(a[f][0]), "r"(a[f][1]), "r"(a[f][2]), "r"(a[f][3]),
                      "r"(b[g][0]), "r"(b[g][1]));
    }

    #pragma unroll
    for (int f = 0; f < 4; f++) {
        const int mrow = bm * 128 + mb + f * 16 + r;
        #pragma unroll
        for (int g = 0; g < 8; g++) {
            const int ncol = nb + g * 8 + 2 * cq;
            const float b0 = bias_s[ncol];
            const float b1 = bias_s[ncol + 1];
            float* d0 = g_xg + (size_t)mrow * GDIM + bn * 256 + ncol;
            *(float2*)d0 = make_float2(acc[f][g][0] + b0, acc[f][g][1] + b1);
            float* d1 = d0 + (size_t)8 * GDIM;
            *(float2*)d1 = make_float2(acc[f][g][2] + b0, acc[f][g][3] + b1);
        }
    }
}

// =====================================================================
// Kernel 2: persistent per-batch LSTM recurrence + classifier head.
// 128 blocks (1 batch each), 256 threads. Warp-local gate pairing:
//   lane-pair (even,odd) owns cell = warp*16 + lane/2;
//   even lane: columns (f_c, g_c); odd lane: (i_c, o_c).
// Gate exchange via shfl.xor(1); cell update redundant in both lanes.
// h double-buffered -> ONE __syncthreads per step.
// Smem weights stored THREAD-INDEXED (slot p / slot 256+p), so the
// permuted gate columns are still read conflict-free (fixes R6's
// 2-way bank conflict between columns c and 128+c).
// =====================================================================
#define SM_Q   8    // 8 quads  -> rows 0..31 in smem
#define REG_Q  24   // 24 quads -> rows 32..127 in registers

__global__ __launch_bounds__(256, 1) void lstm_rec(
    const float* __restrict__ Wh,
    const float* __restrict__ Wc,
    const float* __restrict__ bc,
    float* __restrict__ out)
{
    extern __shared__ char smraw[];
    ulonglong2* Ws = (ulonglong2*)smraw;                 // [SM_Q][512] thread-indexed
    float* h0 = (float*)(smraw + SM_Q * 512 * 16);       // [128] buffer 0
    float* h1 = h0 + 128;                                // [128] buffer 1

    const int p    = threadIdx.x;   // 0..255
    const int b    = blockIdx.x;    // batch element
    const int lane = p & 31;
    const int wid  = p >> 5;
    const int cell = (wid << 4) + (lane >> 1);   // 0..127
    const int odd  = lane & 1;
    // even lane: f (cell), g (256+cell); odd lane: i (128+cell), o (384+cell)
    const int ca = odd ? (128 + cell) : cell;
    const int cb = odd ? (384 + cell) : (256 + cell);

    // ---- stage Wh rows 0..31 into smem, THREAD-INDEXED slots ----
    // slot p       <- column ca (quad-packed)
    // slot 256 + p <- column cb
    #pragma unroll
    for (int q = 0; q < SM_Q; q++) {
        const int k0 = 4 * q;
        ulonglong2 ua, ub;
        ua.x = pack2(__ldg(&Wh[(k0 + 0) * GDIM + ca]), __ldg(&Wh[(k0 + 1) * GDIM + ca]));
        ua.y = pack2(__ldg(&Wh[(k0 + 2) * GDIM + ca]), __ldg(&Wh[(k0 + 3) * GDIM + ca]));
        ub.x = pack2(__ldg(&Wh[(k0 + 0) * GDIM + cb]), __ldg(&Wh[(k0 + 1) * GDIM + cb]));
        ub.y = pack2(__ldg(&Wh[(k0 + 2) * GDIM + cb]), __ldg(&Wh[(k0 + 3) * GDIM + cb]));
        Ws[q * 512 + p]       = ua;
        Ws[q * 512 + 256 + p] = ub;
    }
    // ---- stage Wh rows 32..127 into registers for this thread's columns ----
    ulonglong2 wra[REG_Q], wrb[REG_Q];
    #pragma unroll
    for (int q = 0; q < REG_Q; q++) {
        const int k0 = 4 * SM_Q + 4 * q;
        wra[q].x = pack2(__ldg(&Wh[(k0 + 0) * GDIM + ca]), __ldg(&Wh[(k0 + 1) * GDIM + ca]));
        wra[q].y = pack2(__ldg(&Wh[(k0 + 2) * GDIM + ca]), __ldg(&Wh[(k0 + 3) * GDIM + ca]));
        wrb[q].x = pack2(__ldg(&Wh[(k0 + 0) * GDIM + cb]), __ldg(&Wh[(k0 + 1) * GDIM + cb]));
        wrb[q].y = pack2(__ldg(&Wh[(k0 + 2) * GDIM + cb]), __ldg(&Wh[(k0 + 3) * GDIM + cb]));
    }

    if (p < 128) h0[p] = 0.f;   // t=0 reads buffer 0
    float c_val = 0.f;
    __syncthreads();

    const float* xga = g_xg + (size_t)b * GDIM + ca;
    const float* xgb = g_xg + (size_t)b * GDIM + cb;
    const size_t stepStride = (size_t)BATCH * GDIM;
    float xga_c = __ldg(xga);
    float xga_n = __ldg(xga + stepStride);
    float xgb_c = __ldg(xgb);
    float xgb_n = __ldg(xgb + stepStride);

    const ulonglong2* wsa = Ws + p;
    const ulonglong2* wsb = Ws + 256 + p;

    for (int t = 0; t < S_LEN; t++) {
        const float* h_rd = (t & 1) ? h1 : h0;
        float*       h_wr = (t & 1) ? h0 : h1;
        const ulonglong2* h4 = (const ulonglong2*)h_rd;

        // prefetch xg for t+2 (branch-free clamped index)
        const size_t off = (size_t)((t + 2 < S_LEN) ? (t + 2) : (S_LEN - 1)) * stepStride;
        const float xga_p = __ldg(xga + off);
        const float xgb_p = __ldg(xgb + off);

        ull accA0 = 0ULL, accA1 = 0ULL, accB0 = 0ULL, accB1 = 0ULL;
        // rows 0..31 from smem (thread-indexed, conflict-free)
        #pragma unroll
        for (int q = 0; q < SM_Q; q++) {
            ulonglong2 hv = h4[q];
            ulonglong2 wa = wsa[q * 512];
            ulonglong2 wb = wsb[q * 512];
            FFMA2(accA0, wa.x, hv.x);
            FFMA2(accA1, wa.y, hv.y);
            FFMA2(accB0, wb.x, hv.x);
            FFMA2(accB1, wb.y, hv.y);
        }
        // rows 32..127 from registers
        #pragma unroll
        for (int q = 0; q < REG_Q; q++) {
            ulonglong2 hv = h4[SM_Q + q];
            FFMA2(accA0, wra[q].x, hv.x);
            FFMA2(accA1, wra[q].y, hv.y);
            FFMA2(accB0, wrb[q].x, hv.x);
            FFMA2(accB1, wrb[q].y, hv.y);
        }
        float va = (lo32(accA0) + lo32(accA1)) + (hi32(accA0) + hi32(accA1)) + xga_c;
        float vb = (lo32(accB0) + lo32(accB1)) + (hi32(accB0) + hi32(accB1)) + xgb_c;
        xga_c = xga_n; xga_n = xga_p;
        xgb_c = xgb_n; xgb_n = xgb_p;

        // activations: col a is always sigmoid (f or i);
        // col b: even lane -> tanh (g), odd lane -> sigmoid (o)
        float act_a = fast_sigmoid(va);
        float act_b = odd ? fast_sigmoid(vb) : fast_tanh(vb);

        // exchange with the partner lane
        float ra = __shfl_xor_sync(0xffffffffu, act_a, 1);
        float rb = __shfl_xor_sync(0xffffffffu, act_b, 1);

        const float f_ = odd ? ra    : act_a;
        const float i_ = odd ? act_a : ra;
        const float g_ = odd ? rb    : act_b;
        const float o_ = odd ? act_b : rb;

        c_val = fmaf(f_, c_val, i_ * g_);        // identical in both lanes
        const float h_new = o_ * fast_tanh(c_val);

        if (!odd) h_wr[cell] = h_new;
        __syncthreads();                          // ONE barrier per step
    }

    // final h is in buffer 0 (t=2047 writes h0)
    if (p < 2) {
        float s = __ldg(&bc[p]);
        #pragma unroll 8
        for (int l = 0; l < 128; l++) s += h0[l] * __ldg(&Wc[l * 2 + p]);
        out[b * 2 + p] = s;
    }
}

// =====================================================================
extern "C" void kernel_launch(void* const* d_in, const int* in_sizes, int n_in,
                              void* d_out, int out_size)
{
    const float* x  = (const float*)d_in[0];
    const float* Wi = (const float*)d_in[1];
    const float* bi = (const float*)d_in[2];
    const float* Wh = (const float*)d_in[3];
    const float* bh = (const float*)d_in[4];
    const float* Wc = (const float*)d_in[5];
    const float* bc = (const float*)d_in[6];
    float* out = (float*)d_out;

    const int smemA = (128 * 132 + 128 * 264 + 256) * (int)sizeof(float);  // 203776
    const int smemR = SM_Q * 512 * 16 + 256 * (int)sizeof(float);          // 66560

    cudaFuncSetAttribute(xg_gemm_tf32, cudaFuncAttributeMaxDynamicSharedMemorySize, smemA);
    cudaFuncSetAttribute(lstm_rec,     cudaFuncAttributeMaxDynamicSharedMemorySize, smemR);

    dim3 gridA((S_LEN * BATCH) / 128, GDIM / 256);
    xg_gemm_tf32<<<gridA, 256, smemA>>>(x, Wi, bi, bh);
    lstm_rec<<<BATCH, 256, smemR>>>(Wh, Wc, bc, out);
}

// round 10
// speedup vs baseline: 1.3985x; 1.0894x over previous
#include <cuda_runtime.h>
#include <cstdint>

// Problem dims
#define S_LEN 2048
#define BATCH 128
#define EDIM  128
#define LDIM  128
#define GDIM  512   // 4*LDIM, gate order: f, i, g, o

typedef unsigned long long ull;

// 512 MB scratch for precomputed input projections xg[t][b][512] (bias-folded)
__device__ float g_xg[(size_t)S_LEN * BATCH * GDIM];

// ---------------- packed fp32x2 helpers ----------------
__device__ __forceinline__ ull pack2(float a, float b) {
    ull r;
    asm("mov.b64 %0, {%1, %2};" : "=l"(r) : "f"(a), "f"(b));
    return r;
}
__device__ __forceinline__ float lo32(ull v) {
    float a, b;
    asm("mov.b64 {%0, %1}, %2;" : "=f"(a), "=f"(b) : "l"(v));
    return a;
}
__device__ __forceinline__ float hi32(ull v) {
    float a, b;
    asm("mov.b64 {%0, %1}, %2;" : "=f"(a), "=f"(b) : "l"(v));
    return b;
}
#define FFMA2(acc, a, b) asm("fma.rn.f32x2 %0, %1, %2, %0;" : "+l"(acc) : "l"(a), "l"(b))

// ---------------- fast activations via MUFU.TANH ----------------
__device__ __forceinline__ float fast_tanh(float x) {
    float y;
    asm("tanh.approx.f32 %0, %1;" : "=f"(y) : "f"(x));
    return y;
}
__device__ __forceinline__ float fast_sigmoid(float x) {
    return fmaf(0.5f, fast_tanh(0.5f * x), 0.5f);
}

// =====================================================================
// Kernel 1: xg = x @ Wi + (bi + bh) via tf32 mma.sync  (tensor pipe)
// [M=S*B=262144, N=512, K=128]; block tile 128x256, 256 threads,
// full K resident in smem (As 128x132, Bs 128x264 — conflict-free pads).
// 8 warps as 2(m) x 4(n); warp tile 64x64; m16n8k8 tf32 fragments.
// (measured ~330us; unchanged)
// =====================================================================
__global__ __launch_bounds__(256) void xg_gemm_tf32(
    const float* __restrict__ x,
    const float* __restrict__ Wi,
    const float* __restrict__ bi,
    const float* __restrict__ bh)
{
    extern __shared__ float sm[];
    float* As     = sm;                    // [128][132] tf32 bits
    float* Bs     = sm + 128 * 132;        // [128][264] tf32 bits
    float* bias_s = Bs + 128 * 264;        // [256]

    const int tid = threadIdx.x;
    const int bm  = blockIdx.x;            // 2048 M tiles
    const int bn  = blockIdx.y;            // 2 N tiles

    {
        const int c  = 4 * (tid & 31);
        const int r0 = tid >> 5;
        #pragma unroll
        for (int i = 0; i < 16; i++) {
            const int m = r0 + 8 * i;
            float4 v = *(const float4*)(x + (size_t)(bm * 128 + m) * EDIM + c);
            uint4 u;
            asm("cvt.rna.tf32.f32 %0, %1;" : "=r"(u.x) : "f"(v.x));
            asm("cvt.rna.tf32.f32 %0, %1;" : "=r"(u.y) : "f"(v.y));
            asm("cvt.rna.tf32.f32 %0, %1;" : "=r"(u.z) : "f"(v.z));
            asm("cvt.rna.tf32.f32 %0, %1;" : "=r"(u.w) : "f"(v.w));
            *(uint4*)(As + m * 132 + c) = u;
        }
    }
    {
        const int c  = 4 * (tid & 63);
        const int k0 = tid >> 6;
        #pragma unroll
        for (int i = 0; i < 32; i++) {
            const int k = k0 + 4 * i;
            float4 v = *(const float4*)(Wi + (size_t)k * GDIM + bn * 256 + c);
            uint4 u;
            asm("cvt.rna.tf32.f32 %0, %1;" : "=r"(u.x) : "f"(v.x));
            asm("cvt.rna.tf32.f32 %0, %1;" : "=r"(u.y) : "f"(v.y));
            asm("cvt.rna.tf32.f32 %0, %1;" : "=r"(u.z) : "f"(v.z));
            asm("cvt.rna.tf32.f32 %0, %1;" : "=r"(u.w) : "f"(v.w));
            *(uint4*)(Bs + k * 264 + c) = u;
        }
    }
    bias_s[tid] = bi[bn * 256 + tid] + bh[bn * 256 + tid];
    __syncthreads();

    const int lane = tid & 31;
    const int w    = tid >> 5;
    const int mb   = (w & 1) * 64;
    const int nb   = (w >> 1) * 64;
    const int r    = lane >> 2;
    const int cq   = lane & 3;

    float acc[4][8][4];
    #pragma unroll
    for (int f = 0; f < 4; f++)
        #pragma unroll
        for (int g = 0; g < 8; g++)
            #pragma unroll
            for (int i = 0; i < 4; i++) acc[f][g][i] = 0.f;

    #pragma unroll 4
    for (int s = 0; s < 16; s++) {
        const int k0 = 8 * s;
        uint32_t a[4][4];
        #pragma unroll
        for (int f = 0; f < 4; f++) {
            const float* ap = As + (mb + f * 16 + r) * 132 + k0 + cq;
            a[f][0] = __float_as_uint(ap[0]);
            a[f][1] = __float_as_uint(ap[8 * 132]);
            a[f][2] = __float_as_uint(ap[4]);
            a[f][3] = __float_as_uint(ap[8 * 132 + 4]);
        }
        uint32_t b[8][2];
        #pragma unroll
        for (int g = 0; g < 8; g++) {
            const float* bp = Bs + (k0 + cq) * 264 + nb + g * 8 + r;
            b[g][0] = __float_as_uint(bp[0]);
            b[g][1] = __float_as_uint(bp[4 * 264]);
        }
        #pragma unroll
        for (int f = 0; f < 4; f++)
            #pragma unroll
            for (int g = 0; g < 8; g++)
                asm("mma.sync.aligned.m16n8k8.row.col.f32.tf32.tf32.f32 "
                    "{%0,%1,%2,%3}, {%4,%5,%6,%7}, {%8,%9}, {%0,%1,%2,%3};"
                    : "+f"(acc[f][g][0]), "+f"(acc[f][g][1]),
                      "+f"(acc[f][g][2]), "+f"(acc[f][g][3])
                    : "r"(a[f][0]), "r"(a[f][1]), "r"(a[f][2]), "r"(a[f][3]),
                      "r"(b[g][0]), "r"(b[g][1]));
    }

    #pragma unroll
    for (int f = 0; f < 4; f++) {
        const int mrow = bm * 128 + mb + f * 16 + r;
        #pragma unroll
        for (int g = 0; g < 8; g++) {
            const int ncol = nb + g * 8 + 2 * cq;
            const float b0 = bias_s[ncol];
            const float b1 = bias_s[ncol + 1];
            float* d0 = g_xg + (size_t)mrow * GDIM + bn * 256 + ncol;
            *(float2*)d0 = make_float2(acc[f][g][0] + b0, acc[f][g][1] + b1);
            float* d1 = d0 + (size_t)8 * GDIM;
            *(float2*)d1 = make_float2(acc[f][g][2] + b0, acc[f][g][3] + b1);
        }
    }
}

// =====================================================================
// Kernel 2: persistent per-batch LSTM recurrence + classifier head.
// R5 structure (best measured): 128 blocks (1 batch each), 256 threads,
// 2 gate-columns per thread: thread p handles columns p (f or i) and
// p+256 (g or o); gate exchange via smem, cell update by lower half.
// THIS ROUND: REG_Q 24->26, SM_Q 8->6 (104 of 128 Wh rows register-
// resident; only 24 rows streamed from smem -> weight-LDS 512->384cyc).
// =====================================================================
#define SM_Q   6    // 6 quads  -> rows 0..23 in smem
#define REG_Q  26   // 26 quads -> rows 24..127 in registers

__global__ __launch_bounds__(256, 1) void lstm_rec(
    const float* __restrict__ Wh,
    const float* __restrict__ Wc,
    const float* __restrict__ bc,
    float* __restrict__ out)
{
    extern __shared__ char smraw[];
    ulonglong2* Ws  = (ulonglong2*)smraw;                    // [SM_Q][512]
    float*  h_s  = (float*)(smraw + SM_Q * 512 * 16);        // [128], 16B aligned
    float2* io_s = (float2*)(h_s + 128);                     // [128] (i, o)

    const int p = threadIdx.x;     // 0..255
    const int b = blockIdx.x;      // batch element
    const int ca = p;              // column a: f (p<128) or i (p>=128)
    const int cb = p + 256;        // column b: g (p<128) or o (p>=128)

    // ---- stage Wh rows 0..(4*SM_Q-1) into smem (k-quad packed per column) ----
    #pragma unroll
    for (int q = 0; q < SM_Q; q++) {
        const int k0 = 4 * q;
        #pragma unroll
        for (int s = 0; s < 2; s++) {
            const int col = p + s * 256;
            ulonglong2 u;
            u.x = pack2(__ldg(&Wh[(k0 + 0) * GDIM + col]), __ldg(&Wh[(k0 + 1) * GDIM + col]));
            u.y = pack2(__ldg(&Wh[(k0 + 2) * GDIM + col]), __ldg(&Wh[(k0 + 3) * GDIM + col]));
            Ws[q * 512 + col] = u;
        }
    }
    // ---- stage remaining Wh rows into registers for both columns ----
    ulonglong2 wra[REG_Q], wrb[REG_Q];
    #pragma unroll
    for (int q = 0; q < REG_Q; q++) {
        const int k0 = 4 * SM_Q + 4 * q;
        wra[q].x = pack2(__ldg(&Wh[(k0 + 0) * GDIM + ca]), __ldg(&Wh[(k0 + 1) * GDIM + ca]));
        wra[q].y = pack2(__ldg(&Wh[(k0 + 2) * GDIM + ca]), __ldg(&Wh[(k0 + 3) * GDIM + ca]));
        wrb[q].x = pack2(__ldg(&Wh[(k0 + 0) * GDIM + cb]), __ldg(&Wh[(k0 + 1) * GDIM + cb]));
        wrb[q].y = pack2(__ldg(&Wh[(k0 + 2) * GDIM + cb]), __ldg(&Wh[(k0 + 3) * GDIM + cb]));
    }

    if (p < 128) h_s[p] = 0.f;
    float c_val = 0.f;
    __syncthreads();

    const float* xga = g_xg + (size_t)b * GDIM + ca;
    const float* xgb = g_xg + (size_t)b * GDIM + cb;
    const size_t stepStride = (size_t)BATCH * GDIM;
    float xga_c = __ldg(xga);
    float xga_n = __ldg(xga + stepStride);
    float xgb_c = __ldg(xgb);
    float xgb_n = __ldg(xgb + stepStride);

    const ulonglong2* h4  = (const ulonglong2*)h_s;
    const ulonglong2* wsa = Ws + ca;
    const ulonglong2* wsb = Ws + cb;

    for (int t = 0; t < S_LEN; t++) {
        // prefetch xg for t+2 (branch-free clamped index)
        const size_t off = (size_t)((t + 2 < S_LEN) ? (t + 2) : (S_LEN - 1)) * stepStride;
        const float xga_p = __ldg(xga + off);
        const float xgb_p = __ldg(xgb + off);

        ull accA0 = 0ULL, accA1 = 0ULL, accB0 = 0ULL, accB1 = 0ULL;
        // rows 0..23 from smem
        #pragma unroll
        for (int q = 0; q < SM_Q; q++) {
            ulonglong2 hv = h4[q];
            ulonglong2 wa = wsa[q * 512];
            ulonglong2 wb = wsb[q * 512];
            FFMA2(accA0, wa.x, hv.x);
            FFMA2(accA1, wa.y, hv.y);
            FFMA2(accB0, wb.x, hv.x);
            FFMA2(accB1, wb.y, hv.y);
        }
        // rows 24..127 from registers
        #pragma unroll
        for (int q = 0; q < REG_Q; q++) {
            ulonglong2 hv = h4[SM_Q + q];
            FFMA2(accA0, wra[q].x, hv.x);
            FFMA2(accA1, wra[q].y, hv.y);
            FFMA2(accB0, wrb[q].x, hv.x);
            FFMA2(accB1, wrb[q].y, hv.y);
        }
        float va = (lo32(accA0) + lo32(accA1)) + (hi32(accA0) + hi32(accA1)) + xga_c;
        float vb = (lo32(accB0) + lo32(accB1)) + (hi32(accB0) + hi32(accB1)) + xgb_c;
        xga_c = xga_n; xga_n = xga_p;
        xgb_c = xgb_n; xgb_n = xgb_p;

        float f_act = 0.f, g_act = 0.f;
        if (p < 128) {
            f_act = fast_sigmoid(va);   // forget gate
            g_act = fast_tanh(vb);      // cell candidate
        } else {
            // (i, o) gates -> exchange via smem
            io_s[p - 128] = make_float2(fast_sigmoid(va), fast_sigmoid(vb));
        }
        __syncthreads();

        if (p < 128) {
            float2 io = io_s[p];
            c_val = fmaf(f_act, c_val, io.x * g_act);
            h_s[p] = io.y * fast_tanh(c_val);
        }
        __syncthreads();
    }

    // ---- classifier head: out[b][n] = h @ Wc + bc ----
    if (p < 2) {
        float s = __ldg(&bc[p]);
        #pragma unroll 8
        for (int l = 0; l < 128; l++) s += h_s[l] * __ldg(&Wc[l * 2 + p]);
        out[b * 2 + p] = s;
    }
}

// =====================================================================
extern "C" void kernel_launch(void* const* d_in, const int* in_sizes, int n_in,
                              void* d_out, int out_size)
{
    const float* x  = (const float*)d_in[0];
    const float* Wi = (const float*)d_in[1];
    const float* bi = (const float*)d_in[2];
    const float* Wh = (const float*)d_in[3];
    const float* bh = (const float*)d_in[4];
    const float* Wc = (const float*)d_in[5];
    const float* bc = (const float*)d_in[6];
    float* out = (float*)d_out;

    const int smemA = (128 * 132 + 128 * 264 + 256) * (int)sizeof(float);  // 203776
    const int smemR = SM_Q * 512 * 16 + 128 * (int)sizeof(float)
                    + 128 * (int)sizeof(float2);                           // 50688

    cudaFuncSetAttribute(xg_gemm_tf32, cudaFuncAttributeMaxDynamicSharedMemorySize, smemA);
    cudaFuncSetAttribute(lstm_rec,     cudaFuncAttributeMaxDynamicSharedMemorySize, smemR);

    dim3 gridA((S_LEN * BATCH) / 128, GDIM / 256);
    xg_gemm_tf32<<<gridA, 256, smemA>>>(x, Wi, bi, bh);
    lstm_rec<<<BATCH, 256, smemR>>>(Wh, Wc, bc, out);
}

// round 11
// speedup vs baseline: 1.4161x; 1.0126x over previous
#include <cuda_runtime.h>
#include <cstdint>

// Problem dims
#define S_LEN 2048
#define BATCH 128
#define EDIM  128
#define LDIM  128
#define GDIM  512   // 4*LDIM, gate order: f, i, g, o

typedef unsigned long long ull;

// 512 MB scratch for precomputed input projections xg[t][b][512] (bias-folded)
__device__ float g_xg[(size_t)S_LEN * BATCH * GDIM];

// ---------------- packed fp32x2 helpers ----------------
__device__ __forceinline__ ull pack2(float a, float b) {
    ull r;
    asm("mov.b64 %0, {%1, %2};" : "=l"(r) : "f"(a), "f"(b));
    return r;
}
__device__ __forceinline__ float lo32(ull v) {
    float a, b;
    asm("mov.b64 {%0, %1}, %2;" : "=f"(a), "=f"(b) : "l"(v));
    return a;
}
__device__ __forceinline__ float hi32(ull v) {
    float a, b;
    asm("mov.b64 {%0, %1}, %2;" : "=f"(a), "=f"(b) : "l"(v));
    return b;
}
#define FFMA2(acc, a, b) asm("fma.rn.f32x2 %0, %1, %2, %0;" : "+l"(acc) : "l"(a), "l"(b))

// ---------------- cp.async helper ----------------
#define CP_ASYNC16(dst_u32, src_ptr) \
    asm volatile("cp.async.ca.shared.global [%0], [%1], 16;" \
                 :: "r"(dst_u32), "l"(src_ptr))

// ---------------- fast activations via MUFU.TANH ----------------
__device__ __forceinline__ float fast_tanh(float x) {
    float y;
    asm("tanh.approx.f32 %0, %1;" : "=f"(y) : "f"(x));
    return y;
}
__device__ __forceinline__ float fast_sigmoid(float x) {
    return fmaf(0.5f, fast_tanh(0.5f * x), 0.5f);
}

// =====================================================================
// Kernel 1: xg = x @ Wi + (bi + bh) via tf32 mma.sync  (tensor pipe)
// [M=S*B=262144, N=512, K=128]; block tile 128x256, 256 threads.
// THIS ROUND: 2-stage cp.async K-pipeline (K = 2 x 64). Both stages'
// LDGSTS issued up front; compute of stage 0 overlaps DRAM of stage 1.
// Raw fp32 bits fed to tf32 mma (HW truncates to tf32 — no cvt pass).
// Layouts: As [128][132], Bs [128][264] (conflict-free pads).
// 8 warps as 2(m) x 4(n); warp tile 64x64; m16n8k8 tf32 fragments.
// =====================================================================
__global__ __launch_bounds__(256) void xg_gemm_tf32(
    const float* __restrict__ x,
    const float* __restrict__ Wi,
    const float* __restrict__ bi,
    const float* __restrict__ bh)
{
    extern __shared__ float sm[];
    float* As     = sm;                    // [128][132]
    float* Bs     = sm + 128 * 132;        // [128][264]
    float* bias_s = Bs + 128 * 264;        // [256]

    const int tid = threadIdx.x;
    const int bm  = blockIdx.x;            // 2048 M tiles
    const int bn  = blockIdx.y;            // 2 N tiles

    const uint32_t As_u = (uint32_t)__cvta_generic_to_shared(As);
    const uint32_t Bs_u = (uint32_t)__cvta_generic_to_shared(Bs);

    // ---- issue both K-stages as cp.async (16B granules) ----
    #pragma unroll
    for (int st = 0; st < 2; st++) {
        const int k0 = st * 64;
        // A chunk: 128 rows x 64 k = 2048 float4; 8 per thread
        #pragma unroll
        for (int i = 0; i < 8; i++) {
            const int g   = tid + 256 * i;
            const int row = g >> 4;
            const int kq  = g & 15;
            const uint32_t d = As_u + (uint32_t)(row * 132 + k0 + kq * 4) * 4u;
            const float* s = x + (size_t)(bm * 128 + row) * EDIM + k0 + kq * 4;
            CP_ASYNC16(d, s);
        }
        // B chunk: 64 k-rows x 256 cols = 4096 float4; 16 per thread
        #pragma unroll
        for (int i = 0; i < 16; i++) {
            const int g    = tid + 256 * i;
            const int krow = g >> 6;
            const int nq   = g & 63;
            const uint32_t d = Bs_u + (uint32_t)((k0 + krow) * 264 + nq * 4) * 4u;
            const float* s = Wi + (size_t)(k0 + krow) * GDIM + bn * 256 + nq * 4;
            CP_ASYNC16(d, s);
        }
        asm volatile("cp.async.commit_group;");
    }
    bias_s[tid] = bi[bn * 256 + tid] + bh[bn * 256 + tid];

    const int lane = tid & 31;
    const int w    = tid >> 5;
    const int mb   = (w & 1) * 64;
    const int nb   = (w >> 1) * 64;
    const int r    = lane >> 2;
    const int cq   = lane & 3;

    float acc[4][8][4];
    #pragma unroll
    for (int f = 0; f < 4; f++)
        #pragma unroll
        for (int g = 0; g < 8; g++)
            #pragma unroll
            for (int i = 0; i < 4; i++) acc[f][g][i] = 0.f;

    // ---- stage 0 ready; stage 1 still in flight ----
    asm volatile("cp.async.wait_group 1;");
    __syncthreads();

    #pragma unroll
    for (int half = 0; half < 2; half++) {
        if (half == 1) {
            asm volatile("cp.async.wait_group 0;");
            __syncthreads();
        }
        #pragma unroll 4
        for (int si = 0; si < 8; si++) {
            const int k0 = half * 64 + 8 * si;
            uint32_t a[4][4];
            #pragma unroll
            for (int f = 0; f < 4; f++) {
                const float* ap = As + (mb + f * 16 + r) * 132 + k0 + cq;
                a[f][0] = __float_as_uint(ap[0]);
                a[f][1] = __float_as_uint(ap[8 * 132]);
                a[f][2] = __float_as_uint(ap[4]);
                a[f][3] = __float_as_uint(ap[8 * 132 + 4]);
            }
            uint32_t b[8][2];
            #pragma unroll
            for (int g = 0; g < 8; g++) {
                const float* bp = Bs + (k0 + cq) * 264 + nb + g * 8 + r;
                b[g][0] = __float_as_uint(bp[0]);
                b[g][1] = __float_as_uint(bp[4 * 264]);
            }
            #pragma unroll
            for (int f = 0; f < 4; f++)
                #pragma unroll
                for (int g = 0; g < 8; g++)
                    asm("mma.sync.aligned.m16n8k8.row.col.f32.tf32.tf32.f32 "
                        "{%0,%1,%2,%3}, {%4,%5,%6,%7}, {%8,%9}, {%0,%1,%2,%3};"
                        : "+f"(acc[f][g][0]), "+f"(acc[f][g][1]),
                          "+f"(acc[f][g][2]), "+f"(acc[f][g][3])
                        : "r"(a[f][0]), "r"(a[f][1]), "r"(a[f][2]), "r"(a[f][3]),
                          "r"(b[g][0]), "r"(b[g][1]));
        }
    }

    // ---- epilogue: add bias, store float2 pairs ----
    #pragma unroll
    for (int f = 0; f < 4; f++) {
        const int mrow = bm * 128 + mb + f * 16 + r;
        #pragma unroll
        for (int g = 0; g < 8; g++) {
            const int ncol = nb + g * 8 + 2 * cq;
            const float b0 = bias_s[ncol];
            const float b1 = bias_s[ncol + 1];
            float* d0 = g_xg + (size_t)mrow * GDIM + bn * 256 + ncol;
            *(float2*)d0 = make_float2(acc[f][g][0] + b0, acc[f][g][1] + b1);
            float* d1 = d0 + (size_t)8 * GDIM;
            *(float2*)d1 = make_float2(acc[f][g][2] + b0, acc[f][g][3] + b1);
        }
    }
}

// =====================================================================
// Kernel 2: persistent per-batch LSTM recurrence + classifier head.
// (R10 confirmed-best config: 256 threads, 2 cols/thread, smem gate
// exchange, REG_Q=26/SM_Q=6 — 104 Wh rows register-resident. UNCHANGED)
// =====================================================================
#define SM_Q   6    // 6 quads  -> rows 0..23 in smem
#define REG_Q  26   // 26 quads -> rows 24..127 in registers

__global__ __launch_bounds__(256, 1) void lstm_rec(
    const float* __restrict__ Wh,
    const float* __restrict__ Wc,
    const float* __restrict__ bc,
    float* __restrict__ out)
{
    extern __shared__ char smraw[];
    ulonglong2* Ws  = (ulonglong2*)smraw;                    // [SM_Q][512]
    float*  h_s  = (float*)(smraw + SM_Q * 512 * 16);        // [128], 16B aligned
    float2* io_s = (float2*)(h_s + 128);                     // [128] (i, o)

    const int p = threadIdx.x;     // 0..255
    const int b = blockIdx.x;      // batch element
    const int ca = p;              // column a: f (p<128) or i (p>=128)
    const int cb = p + 256;        // column b: g (p<128) or o (p>=128)

    // ---- stage Wh rows 0..(4*SM_Q-1) into smem (k-quad packed per column) ----
    #pragma unroll
    for (int q = 0; q < SM_Q; q++) {
        const int k0 = 4 * q;
        #pragma unroll
        for (int s = 0; s < 2; s++) {
            const int col = p + s * 256;
            ulonglong2 u;
            u.x = pack2(__ldg(&Wh[(k0 + 0) * GDIM + col]), __ldg(&Wh[(k0 + 1) * GDIM + col]));
            u.y = pack2(__ldg(&Wh[(k0 + 2) * GDIM + col]), __ldg(&Wh[(k0 + 3) * GDIM + col]));
            Ws[q * 512 + col] = u;
        }
    }
    // ---- stage remaining Wh rows into registers for both columns ----
    ulonglong2 wra[REG_Q], wrb[REG_Q];
    #pragma unroll
    for (int q = 0; q < REG_Q; q++) {
        const int k0 = 4 * SM_Q + 4 * q;
        wra[q].x = pack2(__ldg(&Wh[(k0 + 0) * GDIM + ca]), __ldg(&Wh[(k0 + 1) * GDIM + ca]));
        wra[q].y = pack2(__ldg(&Wh[(k0 + 2) * GDIM + ca]), __ldg(&Wh[(k0 + 3) * GDIM + ca]));
        wrb[q].x = pack2(__ldg(&Wh[(k0 + 0) * GDIM + cb]), __ldg(&Wh[(k0 + 1) * GDIM + cb]));
        wrb[q].y = pack2(__ldg(&Wh[(k0 + 2) * GDIM + cb]), __ldg(&Wh[(k0 + 3) * GDIM + cb]));
    }

    if (p < 128) h_s[p] = 0.f;
    float c_val = 0.f;
    __syncthreads();

    const float* xga = g_xg + (size_t)b * GDIM + ca;
    const float* xgb = g_xg + (size_t)b * GDIM + cb;
    const size_t stepStride = (size_t)BATCH * GDIM;
    float xga_c = __ldg(xga);
    float xga_n = __ldg(xga + stepStride);
    float xgb_c = __ldg(xgb);
    float xgb_n = __ldg(xgb + stepStride);

    const ulonglong2* h4  = (const ulonglong2*)h_s;
    const ulonglong2* wsa = Ws + ca;
    const ulonglong2* wsb = Ws + cb;

    for (int t = 0; t < S_LEN; t++) {
        // prefetch xg for t+2 (branch-free clamped index)
        const size_t off = (size_t)((t + 2 < S_LEN) ? (t + 2) : (S_LEN - 1)) * stepStride;
        const float xga_p = __ldg(xga + off);
        const float xgb_p = __ldg(xgb + off);

        ull accA0 = 0ULL, accA1 = 0ULL, accB0 = 0ULL, accB1 = 0ULL;
        // rows 0..23 from smem
        #pragma unroll
        for (int q = 0; q < SM_Q; q++) {
            ulonglong2 hv = h4[q];
            ulonglong2 wa = wsa[q * 512];
            ulonglong2 wb = wsb[q * 512];
            FFMA2(accA0, wa.x, hv.x);
            FFMA2(accA1, wa.y, hv.y);
            FFMA2(accB0, wb.x, hv.x);
            FFMA2(accB1, wb.y, hv.y);
        }
        // rows 24..127 from registers
        #pragma unroll
        for (int q = 0; q < REG_Q; q++) {
            ulonglong2 hv = h4[SM_Q + q];
            FFMA2(accA0, wra[q].x, hv.x);
            FFMA2(accA1, wra[q].y, hv.y);
            FFMA2(accB0, wrb[q].x, hv.x);
            FFMA2(accB1, wrb[q].y, hv.y);
        }
        float va = (lo32(accA0) + lo32(accA1)) + (hi32(accA0) + hi32(accA1)) + xga_c;
        float vb = (lo32(accB0) + lo32(accB1)) + (hi32(accB0) + hi32(accB1)) + xgb_c;
        xga_c = xga_n; xga_n = xga_p;
        xgb_c = xgb_n; xgb_n = xgb_p;

        float f_act = 0.f, g_act = 0.f;
        if (p < 128) {
            f_act = fast_sigmoid(va);   // forget gate
            g_act = fast_tanh(vb);      // cell candidate
        } else {
            // (i, o) gates -> exchange via smem
            io_s[p - 128] = make_float2(fast_sigmoid(va), fast_sigmoid(vb));
        }
        __syncthreads();

        if (p < 128) {
            float2 io = io_s[p];
            c_val = fmaf(f_act, c_val, io.x * g_act);
            h_s[p] = io.y * fast_tanh(c_val);
        }
        __syncthreads();
    }

    // ---- classifier head: out[b][n] = h @ Wc + bc ----
    if (p < 2) {
        float s = __ldg(&bc[p]);
        #pragma unroll 8
        for (int l = 0; l < 128; l++) s += h_s[l] * __ldg(&Wc[l * 2 + p]);
        out[b * 2 + p] = s;
    }
}

// =====================================================================
extern "C" void kernel_launch(void* const* d_in, const int* in_sizes, int n_in,
                              void* d_out, int out_size)
{
    const float* x  = (const float*)d_in[0];
    const float* Wi = (const float*)d_in[1];
    const float* bi = (const float*)d_in[2];
    const float* Wh = (const float*)d_in[3];
    const float* bh = (const float*)d_in[4];
    const float* Wc = (const float*)d_in[5];
    const float* bc = (const float*)d_in[6];
    float* out = (float*)d_out;

    const int smemA = (128 * 132 + 128 * 264 + 256) * (int)sizeof(float);  // 203776
    const int smemR = SM_Q * 512 * 16 + 128 * (int)sizeof(float)
                    + 128 * (int)sizeof(float2);                           // 50688

    cudaFuncSetAttribute(xg_gemm_tf32, cudaFuncAttributeMaxDynamicSharedMemorySize, smemA);
    cudaFuncSetAttribute(lstm_rec,     cudaFuncAttributeMaxDynamicSharedMemorySize, smemR);

    dim3 gridA((S_LEN * BATCH) / 128, GDIM / 256);
    xg_gemm_tf32<<<gridA, 256, smemA>>>(x, Wi, bi, bh);
    lstm_rec<<<BATCH, 256, smemR>>>(Wh, Wc, bc, out);
}

// round 12
// speedup vs baseline: 1.4595x; 1.0306x over previous
#include <cuda_runtime.h>
#include <cstdint>

// Problem dims
#define S_LEN 2048
#define BATCH 128
#define EDIM  128
#define LDIM  128
#define GDIM  512   // 4*LDIM, gate order: f, i, g, o

typedef unsigned long long ull;

// 512 MB scratch for precomputed input projections xg[t][b][512] (bias-folded)
__device__ float g_xg[(size_t)S_LEN * BATCH * GDIM];

// ---------------- packed fp32x2 helpers ----------------
__device__ __forceinline__ ull pack2(float a, float b) {
    ull r;
    asm("mov.b64 %0, {%1, %2};" : "=l"(r) : "f"(a), "f"(b));
    return r;
}
__device__ __forceinline__ float lo32(ull v) {
    float a, b;
    asm("mov.b64 {%0, %1}, %2;" : "=f"(a), "=f"(b) : "l"(v));
    return a;
}
__device__ __forceinline__ float hi32(ull v) {
    float a, b;
    asm("mov.b64 {%0, %1}, %2;" : "=f"(a), "=f"(b) : "l"(v));
    return b;
}
#define FFMA2(acc, a, b) asm("fma.rn.f32x2 %0, %1, %2, %0;" : "+l"(acc) : "l"(a), "l"(b))

// ---------------- cp.async helper ----------------
#define CP_ASYNC16(dst_u32, src_ptr) \
    asm volatile("cp.async.ca.shared.global [%0], [%1], 16;" \
                 :: "r"(dst_u32), "l"(src_ptr))

// ---------------- fast activations via MUFU.TANH ----------------
__device__ __forceinline__ float fast_tanh(float x) {
    float y;
    asm("tanh.approx.f32 %0, %1;" : "=f"(y) : "f"(x));
    return y;
}
__device__ __forceinline__ float fast_sigmoid(float x) {
    return fmaf(0.5f, fast_tanh(0.5f * x), 0.5f);
}

// =====================================================================
// Kernel 1: xg = x @ Wi + (bi + bh) via tf32 mma.sync  (tensor pipe)
// THIS ROUND: occupancy-2 layout. Block tile 128(m) x 128(n), grid
// (4 n-tiles fastest, 2048 m-tiles) so same-bm CTAs share x in L2.
// K pipelined as 4 chunks of 32 with 2 smem stages via cp.async.
// smem 72KB -> 2 CTAs/SM; __launch_bounds__(256,2) caps regs at 128.
// As [2][128][36] (bank perm 4r+cq), Bs [2][32][136] (perm 8cq+r).
// 8 warps as 2(m) x 4(n); warp tile 64x32; m16n8k8 tf32 fragments.
// =====================================================================
#define KC      32          // k per chunk
#define NCHUNK  4
#define AS_STRIDE 36
#define BS_STRIDE 136
#define AS_FLOATS (128 * AS_STRIDE)       // per stage
#define BS_FLOATS (32 * BS_STRIDE)        // per stage

__global__ __launch_bounds__(256, 2) void xg_gemm_tf32(
    const float* __restrict__ x,
    const float* __restrict__ Wi,
    const float* __restrict__ bi,
    const float* __restrict__ bh)
{
    extern __shared__ float sm[];
    float* As     = sm;                              // [2][128][36]
    float* Bs     = sm + 2 * AS_FLOATS;              // [2][32][136]
    float* bias_s = Bs + 2 * BS_FLOATS;              // [128]

    const int tid = threadIdx.x;
    const int bn  = blockIdx.x;            // 4 N tiles (fastest -> L2 x-share)
    const int bm  = blockIdx.y;            // 2048 M tiles

    const uint32_t As_u = (uint32_t)__cvta_generic_to_shared(As);
    const uint32_t Bs_u = (uint32_t)__cvta_generic_to_shared(Bs);

    const float* xbase  = x  + (size_t)bm * 128 * EDIM;
    const float* wibase = Wi + (size_t)bn * 128;

    // ---- chunk loader: chunk c -> stage s ----
    auto issue_chunk = [&](int c, int s) {
        const int kc0 = c * KC;
        // A: 128 rows x 32 k = 1024 granules(16B); 4 per thread
        #pragma unroll
        for (int i = 0; i < 4; i++) {
            const int g   = tid + 256 * i;
            const int row = g >> 3;
            const int kq  = g & 7;
            const uint32_t d = As_u + (uint32_t)((s * AS_FLOATS) + row * AS_STRIDE + kq * 4) * 4u;
            CP_ASYNC16(d, xbase + (size_t)row * EDIM + kc0 + kq * 4);
        }
        // B: 32 k-rows x 128 n = 1024 granules; 4 per thread
        #pragma unroll
        for (int i = 0; i < 4; i++) {
            const int g    = tid + 256 * i;
            const int krow = g >> 5;
            const int nq   = g & 31;
            const uint32_t d = Bs_u + (uint32_t)((s * BS_FLOATS) + krow * BS_STRIDE + nq * 4) * 4u;
            CP_ASYNC16(d, wibase + (size_t)(kc0 + krow) * GDIM + nq * 4);
        }
        asm volatile("cp.async.commit_group;");
    };

    issue_chunk(0, 0);
    issue_chunk(1, 1);
    if (tid < 128) bias_s[tid] = bi[bn * 128 + tid] + bh[bn * 128 + tid];

    const int lane = tid & 31;
    const int w    = tid >> 5;
    const int mb   = (w & 1) * 64;         // warp m base
    const int nb   = (w >> 1) * 32;        // warp n base
    const int r    = lane >> 2;            // 0..7
    const int cq   = lane & 3;             // 0..3

    float acc[4][4][4];
    #pragma unroll
    for (int f = 0; f < 4; f++)
        #pragma unroll
        for (int g = 0; g < 4; g++)
            #pragma unroll
            for (int i = 0; i < 4; i++) acc[f][g][i] = 0.f;

    #pragma unroll
    for (int c = 0; c < NCHUNK; c++) {
        if (c < NCHUNK - 1) asm volatile("cp.async.wait_group 1;");
        else                asm volatile("cp.async.wait_group 0;");
        __syncthreads();

        const int s = c & 1;
        const float* Asb = As + s * AS_FLOATS;
        const float* Bsb = Bs + s * BS_FLOATS;

        #pragma unroll
        for (int si = 0; si < 4; si++) {
            const int k0 = 8 * si;
            uint32_t a[4][4];
            #pragma unroll
            for (int f = 0; f < 4; f++) {
                const float* ap = Asb + (mb + f * 16 + r) * AS_STRIDE + k0 + cq;
                a[f][0] = __float_as_uint(ap[0]);
                a[f][1] = __float_as_uint(ap[8 * AS_STRIDE]);
                a[f][2] = __float_as_uint(ap[4]);
                a[f][3] = __float_as_uint(ap[8 * AS_STRIDE + 4]);
            }
            uint32_t b[4][2];
            #pragma unroll
            for (int g = 0; g < 4; g++) {
                const float* bp = Bsb + (k0 + cq) * BS_STRIDE + nb + g * 8 + r;
                b[g][0] = __float_as_uint(bp[0]);
                b[g][1] = __float_as_uint(bp[4 * BS_STRIDE]);
            }
            #pragma unroll
            for (int f = 0; f < 4; f++)
                #pragma unroll
                for (int g = 0; g < 4; g++)
                    asm("mma.sync.aligned.m16n8k8.row.col.f32.tf32.tf32.f32 "
                        "{%0,%1,%2,%3}, {%4,%5,%6,%7}, {%8,%9}, {%0,%1,%2,%3};"
                        : "+f"(acc[f][g][0]), "+f"(acc[f][g][1]),
                          "+f"(acc[f][g][2]), "+f"(acc[f][g][3])
                        : "r"(a[f][0]), "r"(a[f][1]), "r"(a[f][2]), "r"(a[f][3]),
                          "r"(b[g][0]), "r"(b[g][1]));
        }

        if (c < NCHUNK - 2) {
            __syncthreads();               // stage s fully consumed
            issue_chunk(c + 2, s);
        }
    }

    // ---- epilogue: add bias, store float2 pairs ----
    #pragma unroll
    for (int f = 0; f < 4; f++) {
        const int mrow = bm * 128 + mb + f * 16 + r;
        #pragma unroll
        for (int g = 0; g < 4; g++) {
            const int ncol = nb + g * 8 + 2 * cq;
            const float b0 = bias_s[ncol];
            const float b1 = bias_s[ncol + 1];
            float* d0 = g_xg + (size_t)mrow * GDIM + bn * 128 + ncol;
            *(float2*)d0 = make_float2(acc[f][g][0] + b0, acc[f][g][1] + b1);
            float* d1 = d0 + (size_t)8 * GDIM;
            *(float2*)d1 = make_float2(acc[f][g][2] + b0, acc[f][g][3] + b1);
        }
    }
}

// =====================================================================
// Kernel 2: persistent per-batch LSTM recurrence + classifier head.
// (R10 confirmed-best config: 256 threads, 2 cols/thread, smem gate
// exchange, REG_Q=26/SM_Q=6 — 104 Wh rows register-resident. UNCHANGED)
// =====================================================================
#define SM_Q   6    // 6 quads  -> rows 0..23 in smem
#define REG_Q  26   // 26 quads -> rows 24..127 in registers

__global__ __launch_bounds__(256, 1) void lstm_rec(
    const float* __restrict__ Wh,
    const float* __restrict__ Wc,
    const float* __restrict__ bc,
    float* __restrict__ out)
{
    extern __shared__ char smraw[];
    ulonglong2* Ws  = (ulonglong2*)smraw;                    // [SM_Q][512]
    float*  h_s  = (float*)(smraw + SM_Q * 512 * 16);        // [128], 16B aligned
    float2* io_s = (float2*)(h_s + 128);                     // [128] (i, o)

    const int p = threadIdx.x;     // 0..255
    const int b = blockIdx.x;      // batch element
    const int ca = p;              // column a: f (p<128) or i (p>=128)
    const int cb = p + 256;        // column b: g (p<128) or o (p>=128)

    // ---- stage Wh rows 0..(4*SM_Q-1) into smem (k-quad packed per column) ----
    #pragma unroll
    for (int q = 0; q < SM_Q; q++) {
        const int k0 = 4 * q;
        #pragma unroll
        for (int s = 0; s < 2; s++) {
            const int col = p + s * 256;
            ulonglong2 u;
            u.x = pack2(__ldg(&Wh[(k0 + 0) * GDIM + col]), __ldg(&Wh[(k0 + 1) * GDIM + col]));
            u.y = pack2(__ldg(&Wh[(k0 + 2) * GDIM + col]), __ldg(&Wh[(k0 + 3) * GDIM + col]));
            Ws[q * 512 + col] = u;
        }
    }
    // ---- stage remaining Wh rows into registers for both columns ----
    ulonglong2 wra[REG_Q], wrb[REG_Q];
    #pragma unroll
    for (int q = 0; q < REG_Q; q++) {
        const int k0 = 4 * SM_Q + 4 * q;
        wra[q].x = pack2(__ldg(&Wh[(k0 + 0) * GDIM + ca]), __ldg(&Wh[(k0 + 1) * GDIM + ca]));
        wra[q].y = pack2(__ldg(&Wh[(k0 + 2) * GDIM + ca]), __ldg(&Wh[(k0 + 3) * GDIM + ca]));
        wrb[q].x = pack2(__ldg(&Wh[(k0 + 0) * GDIM + cb]), __ldg(&Wh[(k0 + 1) * GDIM + cb]));
        wrb[q].y = pack2(__ldg(&Wh[(k0 + 2) * GDIM + cb]), __ldg(&Wh[(k0 + 3) * GDIM + cb]));
    }

    if (p < 128) h_s[p] = 0.f;
    float c_val = 0.f;
    __syncthreads();

    const float* xga = g_xg + (size_t)b * GDIM + ca;
    const float* xgb = g_xg + (size_t)b * GDIM + cb;
    const size_t stepStride = (size_t)BATCH * GDIM;
    float xga_c = __ldg(xga);
    float xga_n = __ldg(xga + stepStride);
    float xgb_c = __ldg(xgb);
    float xgb_n = __ldg(xgb + stepStride);

    const ulonglong2* h4  = (const ulonglong2*)h_s;
    const ulonglong2* wsa = Ws + ca;
    const ulonglong2* wsb = Ws + cb;

    for (int t = 0; t < S_LEN; t++) {
        // prefetch xg for t+2 (branch-free clamped index)
        const size_t off = (size_t)((t + 2 < S_LEN) ? (t + 2) : (S_LEN - 1)) * stepStride;
        const float xga_p = __ldg(xga + off);
        const float xgb_p = __ldg(xgb + off);

        ull accA0 = 0ULL, accA1 = 0ULL, accB0 = 0ULL, accB1 = 0ULL;
        // rows 0..23 from smem
        #pragma unroll
        for (int q = 0; q < SM_Q; q++) {
            ulonglong2 hv = h4[q];
            ulonglong2 wa = wsa[q * 512];
            ulonglong2 wb = wsb[q * 512];
            FFMA2(accA0, wa.x, hv.x);
            FFMA2(accA1, wa.y, hv.y);
            FFMA2(accB0, wb.x, hv.x);
            FFMA2(accB1, wb.y, hv.y);
        }
        // rows 24..127 from registers
        #pragma unroll
        for (int q = 0; q < REG_Q; q++) {
            ulonglong2 hv = h4[SM_Q + q];
            FFMA2(accA0, wra[q].x, hv.x);
            FFMA2(accA1, wra[q].y, hv.y);
            FFMA2(accB0, wrb[q].x, hv.x);
            FFMA2(accB1, wrb[q].y, hv.y);
        }
        float va = (lo32(accA0) + lo32(accA1)) + (hi32(accA0) + hi32(accA1)) + xga_c;
        float vb = (lo32(accB0) + lo32(accB1)) + (hi32(accB0) + hi32(accB1)) + xgb_c;
        xga_c = xga_n; xga_n = xga_p;
        xgb_c = xgb_n; xgb_n = xgb_p;

        float f_act = 0.f, g_act = 0.f;
        if (p < 128) {
            f_act = fast_sigmoid(va);   // forget gate
            g_act = fast_tanh(vb);      // cell candidate
        } else {
            // (i, o) gates -> exchange via smem
            io_s[p - 128] = make_float2(fast_sigmoid(va), fast_sigmoid(vb));
        }
        __syncthreads();

        if (p < 128) {
            float2 io = io_s[p];
            c_val = fmaf(f_act, c_val, io.x * g_act);
            h_s[p] = io.y * fast_tanh(c_val);
        }
        __syncthreads();
    }

    // ---- classifier head: out[b][n] = h @ Wc + bc ----
    if (p < 2) {
        float s = __ldg(&bc[p]);
        #pragma unroll 8
        for (int l = 0; l < 128; l++) s += h_s[l] * __ldg(&Wc[l * 2 + p]);
        out[b * 2 + p] = s;
    }
}

// =====================================================================
extern "C" void kernel_launch(void* const* d_in, const int* in_sizes, int n_in,
                              void* d_out, int out_size)
{
    const float* x  = (const float*)d_in[0];
    const float* Wi = (const float*)d_in[1];
    const float* bi = (const float*)d_in[2];
    const float* Wh = (const float*)d_in[3];
    const float* bh = (const float*)d_in[4];
    const float* Wc = (const float*)d_in[5];
    const float* bc = (const float*)d_in[6];
    float* out = (float*)d_out;

    const int smemA = (2 * AS_FLOATS + 2 * BS_FLOATS + 128) * (int)sizeof(float); // 72192
    const int smemR = SM_Q * 512 * 16 + 128 * (int)sizeof(float)
                    + 128 * (int)sizeof(float2);                                  // 50688

    cudaFuncSetAttribute(xg_gemm_tf32, cudaFuncAttributeMaxDynamicSharedMemorySize, smemA);
    cudaFuncSetAttribute(lstm_rec,     cudaFuncAttributeMaxDynamicSharedMemorySize, smemR);

    dim3 gridA(GDIM / 128, (S_LEN * BATCH) / 128);   // bn fastest -> x shared in L2
    xg_gemm_tf32<<<gridA, 256, smemA>>>(x, Wi, bi, bh);
    lstm_rec<<<BATCH, 256, smemR>>>(Wh, Wc, bc, out);
}